// round 6
// baseline (speedup 1.0000x reference)
#include <cuda_runtime.h>
#include <cuda_bf16.h>
#include <stdint.h>
#include <math.h>

#define N_NODES 10000
#define N_EDGES 100000
#define F_NODE 128
#define F_EDGE 16
#define HEADS 8
#define OUT_CH 128
#define HC 1024
#define NQKVS 3200   // 3*1024 + 128 fused output columns

// ---------------- scratch (device globals) ----------------
__device__ __nv_bfloat16 d_xh[N_NODES * 128];
__device__ __nv_bfloat16 d_xl[N_NODES * 128];
__device__ __nv_bfloat16 d_qb[N_NODES * HC];
__device__ __nv_bfloat16 d_kb[N_NODES * HC];
__device__ __nv_bfloat16 d_vb[N_NODES * HC];
__device__ __nv_bfloat16 d_Bb[N_NODES * 128];
__device__ __nv_bfloat16 d_Wqh[128 * NQKVS];
__device__ __nv_bfloat16 d_Wql[128 * NQKVS];
__device__ __nv_bfloat16 d_Wgh[1024 * 128];
__device__ __nv_bfloat16 d_Wgl[1024 * 128];
__device__ __nv_bfloat16 d_Werh[128 * 128];
__device__ __nv_bfloat16 d_Werl[128 * 128];
__device__ float d_biasc[NQKVS];
__device__ float d_skip[N_NODES * 128];
__device__ float d_g[N_NODES * 128];
__device__ float d_aexp[N_EDGES * HEADS];
__device__ float d_s[N_NODES * HEADS];
__device__ float d_vout[N_NODES * 128];
__device__ float d_B[N_NODES * 128];
__device__ float d_pooled[128];

// ---------------- fused prep: split_x | pack_w | bias | build_wg | build_wer ----
#define SEG0 (N_NODES * 128)
#define SEG1 (128 * NQKVS)
#define SEG2 (NQKVS)
#define SEG3 (1024 * 128)
#define SEG4 (128 * 128)
#define PREP_TOTAL (SEG0 + SEG1 + SEG2 + SEG3 + SEG4)

__global__ __launch_bounds__(256) void prep_all(
    const float* __restrict__ x, const float* __restrict__ Wq,
    const float* __restrict__ Wk, const float* __restrict__ Wv,
    const float* __restrict__ Ws, const float* __restrict__ bq,
    const float* __restrict__ bk, const float* __restrict__ bv,
    const float* __restrict__ bs, const float* __restrict__ We) {
    int idx = blockIdx.x * 256 + threadIdx.x;
    if (idx < SEG0) {
        float v = x[idx];
        __nv_bfloat16 h = __float2bfloat16(v);
        d_xh[idx] = h;
        d_xl[idx] = __float2bfloat16(v - __bfloat162float(h));
        return;
    }
    idx -= SEG0;
    if (idx < SEG1) {
        int k = idx / NQKVS, col = idx % NQKVS;
        float v;
        if (col < 1024) v = Wq[k * HC + col];
        else if (col < 2048) v = Wk[k * HC + col - 1024];
        else if (col < 3072) v = Wv[k * HC + col - 2048];
        else v = Ws[k * 128 + col - 3072];
        __nv_bfloat16 h = __float2bfloat16(v);
        d_Wqh[idx] = h;
        d_Wql[idx] = __float2bfloat16(v - __bfloat162float(h));
        return;
    }
    idx -= SEG1;
    if (idx < SEG2) {
        float b;
        if (idx < 1024) b = bq[idx];
        else if (idx < 2048) b = bk[idx - 1024];
        else if (idx < 3072) b = bv[idx - 2048];
        else b = bs[idx - 3072];
        d_biasc[idx] = b;
        return;
    }
    idx -= SEG2;
    if (idx < SEG3) {
        int k = idx >> 7, j = idx & 127;
        int h = j >> 4, f = j & 15;
        int c = k & 127, hk = k >> 7;
        float v = (hk == h) ? We[f * HC + h * 128 + c] : 0.f;
        __nv_bfloat16 hh = __float2bfloat16(v);
        d_Wgh[idx] = hh;
        d_Wgl[idx] = __float2bfloat16(v - __bfloat162float(hh));
        return;
    }
    idx -= SEG3;
    if (idx < SEG4) {
        int j = idx >> 7, c = idx & 127;
        int h = j >> 4, f = j & 15;
        float v = We[f * HC + h * 128 + c];
        __nv_bfloat16 hh = __float2bfloat16(v);
        d_Werh[idx] = hh;
        d_Werl[idx] = __float2bfloat16(v - __bfloat162float(hh));
    }
}

__global__ void split_B() {
    int i = blockIdx.x * 256 + threadIdx.x;
    if (i < N_NODES * 128) d_Bb[i] = __float2bfloat16(d_B[i]);
}

// ---------------- MMA helpers ----------------
__device__ __forceinline__ void ldsm4(uint32_t* r, const void* p) {
    unsigned a = (unsigned)__cvta_generic_to_shared(p);
    asm volatile("ldmatrix.sync.aligned.m8n8.x4.shared.b16 {%0,%1,%2,%3}, [%4];\n"
                 : "=r"(r[0]), "=r"(r[1]), "=r"(r[2]), "=r"(r[3]) : "r"(a));
}
__device__ __forceinline__ void ldsm4t(uint32_t* r, const void* p) {
    unsigned a = (unsigned)__cvta_generic_to_shared(p);
    asm volatile("ldmatrix.sync.aligned.m8n8.x4.trans.shared.b16 {%0,%1,%2,%3}, [%4];\n"
                 : "=r"(r[0]), "=r"(r[1]), "=r"(r[2]), "=r"(r[3]) : "r"(a));
}
__device__ __forceinline__ void mma_bf16(float* c, const uint32_t* a, uint32_t b0,
                                         uint32_t b1) {
    asm volatile(
        "mma.sync.aligned.m16n8k16.row.col.f32.bf16.bf16.f32 "
        "{%0,%1,%2,%3}, {%4,%5,%6,%7}, {%8,%9}, {%0,%1,%2,%3};\n"
        : "+f"(c[0]), "+f"(c[1]), "+f"(c[2]), "+f"(c[3])
        : "r"(a[0]), "r"(a[1]), "r"(a[2]), "r"(a[3]), "r"(b0), "r"(b1));
}
__device__ __forceinline__ void cp16(void* sdst, const void* gsrc, bool pred) {
    unsigned s = (unsigned)__cvta_generic_to_shared(sdst);
    int sz = pred ? 16 : 0;
    asm volatile("cp.async.cg.shared.global [%0], [%1], 16, %2;\n" ::"r"(s), "l"(gsrc),
                 "r"(sz));
}

// ---------------- unified TC GEMM, double-buffered, pre-split bf16 ----------------
__global__ __launch_bounds__(256) void gemm_tc(int asel, int wsel, int osel, int M,
                                               int N, int Kstride, int kcount) {
    const __nv_bfloat16 *Ah, *Al = nullptr, *Wh, *Wl;
    if (asel == 0) { Ah = d_xh; Al = d_xl; }
    else if (asel == 1) Ah = d_qb;
    else Ah = d_Bb;
    if (wsel == 0) { Wh = d_Wqh; Wl = d_Wql; }
    else if (wsel == 1) { Wh = d_Wgh; Wl = d_Wgl; }
    else { Wh = d_Werh; Wl = d_Werl; }
    const bool has_al = (asel == 0);

    extern __shared__ __align__(16) char dyn[];
    __nv_bfloat16* dynb = (__nv_bfloat16*)dyn;
    float* spool = (float*)(dyn + 59392);

    int tid = threadIdx.x, w = tid >> 5, l = tid & 31;
    int bm = blockIdx.y * 128, bn = blockIdx.x * 64;
    int wm = (w >> 1) * 32, wn = (w & 1) * 32;
    int kbeg = (wsel == 1) ? blockIdx.x * 512 : 0;
    if (osel == 2 && tid < 64) spool[tid] = 0.f;

    float acc[2][4][4];
#pragma unroll
    for (int a = 0; a < 2; a++)
#pragma unroll
        for (int b = 0; b < 4; b++)
#pragma unroll
            for (int c = 0; c < 4; c++) acc[a][b][c] = 0.f;

    int a_r = (l & 7) + ((l >> 3) & 1) * 8;
    int a_ko = ((l >> 4) & 1) * 8;

    auto pA = [&](int st, int p) { return dynb + (st * 2 + p) * 5120; };
    auto pW = [&](int st, int p) { return dynb + 20480 + (st * 2 + p) * 2304; };

    auto load_stage = [&](int st, int kc) {
        int nh = has_al ? 2 : 1;
        for (int p = 0; p < nh; p++) {
            const __nv_bfloat16* As = p ? Al : Ah;
            __nv_bfloat16* dst = pA(st, p);
#pragma unroll
            for (int i = 0; i < 2; i++) {
                int idx = tid + 256 * i;
                int row = idx >> 2, ch = idx & 3;
                int gr = bm + row;
                cp16(dst + row * 40 + ch * 8, As + (size_t)gr * Kstride + kc + ch * 8,
                     gr < M);
            }
        }
        for (int p = 0; p < 2; p++) {
            const __nv_bfloat16* Ws = p ? Wl : Wh;
            __nv_bfloat16* dst = pW(st, p);
            int k = tid >> 3, ch = tid & 7;
            cp16(dst + k * 72 + ch * 8, Ws + (size_t)(kc + k) * N + bn + ch * 8, true);
        }
        asm volatile("cp.async.commit_group;\n" ::);
    };

    auto compute = [&](int st) {
#pragma unroll
        for (int k16 = 0; k16 < 2; k16++) {
            uint32_t Af[2][4], Alf[2][4], Bhf[2][4], Blf[2][4];
            __nv_bfloat16* ah = pA(st, 0);
#pragma unroll
            for (int mt = 0; mt < 2; mt++)
                ldsm4(Af[mt], ah + (wm + mt * 16 + a_r) * 40 + k16 * 16 + a_ko);
            __nv_bfloat16* wh = pW(st, 0);
            __nv_bfloat16* wl = pW(st, 1);
#pragma unroll
            for (int p = 0; p < 2; p++) {
                ldsm4t(Bhf[p], wh + (k16 * 16 + a_r) * 72 + wn + p * 16 + a_ko);
                ldsm4t(Blf[p], wl + (k16 * 16 + a_r) * 72 + wn + p * 16 + a_ko);
            }
            if (has_al) {
                __nv_bfloat16* al = pA(st, 1);
#pragma unroll
                for (int mt = 0; mt < 2; mt++)
                    ldsm4(Alf[mt], al + (wm + mt * 16 + a_r) * 40 + k16 * 16 + a_ko);
            }
#pragma unroll
            for (int nt = 0; nt < 4; nt++) {
                uint32_t bh0 = Bhf[nt >> 1][(nt & 1) * 2], bh1 = Bhf[nt >> 1][(nt & 1) * 2 + 1];
                uint32_t bl0 = Blf[nt >> 1][(nt & 1) * 2], bl1 = Blf[nt >> 1][(nt & 1) * 2 + 1];
#pragma unroll
                for (int mt = 0; mt < 2; mt++) {
                    mma_bf16(acc[mt][nt], Af[mt], bh0, bh1);
                    mma_bf16(acc[mt][nt], Af[mt], bl0, bl1);
                    if (has_al) mma_bf16(acc[mt][nt], Alf[mt], bh0, bh1);
                }
            }
        }
    };

    int nIter = kcount >> 5;
    load_stage(0, kbeg);
    for (int it = 0; it < nIter; it++) {
        if (it + 1 < nIter) {
            load_stage((it + 1) & 1, kbeg + (it + 1) * 32);
            asm volatile("cp.async.wait_group 1;\n" ::);
        } else {
            asm volatile("cp.async.wait_group 0;\n" ::);
        }
        __syncthreads();
        compute(it & 1);
        __syncthreads();
    }

    int r0 = l >> 2, cq = (l & 3) * 2;
    if (osel == 0) {
        __nv_bfloat16* dstb = nullptr;
        float* dstf = nullptr;
        int coff;
        if (bn < 1024) { dstb = d_qb; coff = bn; }
        else if (bn < 2048) { dstb = d_kb; coff = bn - 1024; }
        else if (bn < 3072) { dstb = d_vb; coff = bn - 2048; }
        else { dstf = d_skip; coff = bn - 3072; }
#pragma unroll
        for (int mt = 0; mt < 2; mt++)
#pragma unroll
            for (int nt = 0; nt < 4; nt++) {
                int gcol = bn + wn + nt * 8 + cq;
                int col = coff + wn + nt * 8 + cq;
                float bb0 = d_biasc[gcol], bb1 = d_biasc[gcol + 1];
#pragma unroll
                for (int rr = 0; rr < 2; rr++) {
                    int row = bm + wm + mt * 16 + r0 + rr * 8;
                    if (row < M) {
                        float v0 = acc[mt][nt][rr * 2] + bb0;
                        float v1 = acc[mt][nt][rr * 2 + 1] + bb1;
                        if (dstf) {
                            dstf[row * 128 + col] = v0;
                            dstf[row * 128 + col + 1] = v1;
                        } else {
                            *(__nv_bfloat162*)&dstb[(size_t)row * HC + col] =
                                __floats2bfloat162_rn(v0, v1);
                        }
                    }
                }
            }
    } else if (osel == 1) {
#pragma unroll
        for (int mt = 0; mt < 2; mt++)
#pragma unroll
            for (int nt = 0; nt < 4; nt++) {
                int col = bn + wn + nt * 8 + cq;
#pragma unroll
                for (int rr = 0; rr < 2; rr++) {
                    int row = bm + wm + mt * 16 + r0 + rr * 8;
                    if (row < M) {
                        d_g[row * 128 + col] = acc[mt][nt][rr * 2];
                        d_g[row * 128 + col + 1] = acc[mt][nt][rr * 2 + 1];
                    }
                }
            }
    } else {
#pragma unroll
        for (int nt = 0; nt < 4; nt++) {
            int col = bn + wn + nt * 8 + cq;
            float s0 = 0.f, s1 = 0.f;
#pragma unroll
            for (int mt = 0; mt < 2; mt++)
#pragma unroll
                for (int rr = 0; rr < 2; rr++) {
                    int row = bm + wm + mt * 16 + r0 + rr * 8;
                    if (row < M) {
                        s0 += fmaxf(acc[mt][nt][rr * 2] + d_vout[row * 128 + col] +
                                        d_skip[row * 128 + col], 0.f);
                        s1 += fmaxf(acc[mt][nt][rr * 2 + 1] + d_vout[row * 128 + col + 1] +
                                        d_skip[row * 128 + col + 1], 0.f);
                    }
                }
#pragma unroll
            for (int off = 16; off >= 4; off >>= 1) {
                s0 += __shfl_xor_sync(0xffffffffu, s0, off);
                s1 += __shfl_xor_sync(0xffffffffu, s1, off);
            }
            if (l < 4) {
                atomicAdd(&spool[wn + nt * 8 + cq], s0);
                atomicAdd(&spool[wn + nt * 8 + cq + 1], s1);
            }
        }
        __syncthreads();
        if (tid < 64) atomicAdd(&d_pooled[bn + tid], spool[tid]);
    }
}

// ---------------- edge helpers ----------------
__device__ __forceinline__ float dot8(uint4 a, uint4 b) {
    float2 a0 = __bfloat1622float2(*(__nv_bfloat162*)&a.x);
    float2 a1 = __bfloat1622float2(*(__nv_bfloat162*)&a.y);
    float2 a2 = __bfloat1622float2(*(__nv_bfloat162*)&a.z);
    float2 a3 = __bfloat1622float2(*(__nv_bfloat162*)&a.w);
    float2 b0 = __bfloat1622float2(*(__nv_bfloat162*)&b.x);
    float2 b1 = __bfloat1622float2(*(__nv_bfloat162*)&b.y);
    float2 b2 = __bfloat1622float2(*(__nv_bfloat162*)&b.z);
    float2 b3 = __bfloat1622float2(*(__nv_bfloat162*)&b.w);
    return a0.x * b0.x + a0.y * b0.y + a1.x * b1.x + a1.y * b1.y + a2.x * b2.x +
           a2.y * b2.y + a3.x * b3.x + a3.y * b3.y;
}

// ---------------- edge pass A: alpha, warp/edge, lane-contiguous gathers --------
// lane l covers bf16 channels {chunk j*256} + l*8..+8 -> per-chunk partial is for
// head 2j + (l>>4); reduce within 16-lane halves, assemble on lanes 0..7.
__global__ __launch_bounds__(256) void edge_alpha(const float* __restrict__ ea,
                                                  const int* __restrict__ eidx) {
    int e = blockIdx.x * 8 + threadIdx.y;
    if (e >= N_EDGES) return;
    int l = threadIdx.x;
    int src = __ldg(&eidx[e]);
    int dst = __ldg(&eidx[N_EDGES + e]);
    const __nv_bfloat16* qp = &d_qb[(size_t)dst * HC + l * 8];
    const __nv_bfloat16* kp = &d_kb[(size_t)src * HC + l * 8];
    float pd0 = dot8(*(const uint4*)(qp), *(const uint4*)(kp));
    float pd1 = dot8(*(const uint4*)(qp + 256), *(const uint4*)(kp + 256));
    float pd2 = dot8(*(const uint4*)(qp + 512), *(const uint4*)(kp + 512));
    float pd3 = dot8(*(const uint4*)(qp + 768), *(const uint4*)(kp + 768));
#pragma unroll
    for (int off = 1; off <= 8; off <<= 1) {
        pd0 += __shfl_xor_sync(0xffffffffu, pd0, off);
        pd1 += __shfl_xor_sync(0xffffffffu, pd1, off);
        pd2 += __shfl_xor_sync(0xffffffffu, pd2, off);
        pd3 += __shfl_xor_sync(0xffffffffu, pd3, off);
    }
    // edge term: partial for head l>>2 over f=(l&3)*4..+4
    float4 g4 = *(const float4*)&d_g[dst * 128 + l * 4];
    float4 e4 = *(const float4*)&ea[e * F_EDGE + (l & 3) * 4];
    float et = g4.x * e4.x + g4.y * e4.y + g4.z * e4.z + g4.w * e4.w;
    et += __shfl_xor_sync(0xffffffffu, et, 1);
    et += __shfl_xor_sync(0xffffffffu, et, 2);
    // assemble per-head alpha on lanes 0..7 (head = l, = 2*(l>>1) + (l&1))
    int hsrc = (l & 1) * 16;
    float kd0 = __shfl_sync(0xffffffffu, pd0, hsrc);
    float kd1 = __shfl_sync(0xffffffffu, pd1, hsrc);
    float kd2 = __shfl_sync(0xffffffffu, pd2, hsrc);
    float kd3 = __shfl_sync(0xffffffffu, pd3, hsrc);
    float etl = __shfl_sync(0xffffffffu, et, (l & 7) * 4);
    if (l < 8) {
        int jj = l >> 1;
        float kd = (jj == 0) ? kd0 : (jj == 1) ? kd1 : (jj == 2) ? kd2 : kd3;
        float aex = __expf((kd + etl) * 0.08838834764831845f);
        d_aexp[e * 8 + l] = aex;
        atomicAdd(&d_s[dst * 8 + l], aex);
    }
}

// ---------------- edge pass B: v-term (coalesced) + B scatter (R4-exact) --------
__global__ __launch_bounds__(256) void edge_msg(const float* __restrict__ ea,
                                                const int* __restrict__ eidx) {
    int e = blockIdx.x * 8 + threadIdx.y;
    if (e >= N_EDGES) return;
    int l = threadIdx.x;
    int src = __ldg(&eidx[e]);
    int dst = __ldg(&eidx[N_EDGES + e]);
    float an = 0.f;
    if (l < 8) {
        float s = d_s[dst * 8 + l];
        an = 0.125f * d_aexp[e * 8 + l] / (s + 1e-16f);
    }
    int h2 = l >> 4, c8 = l & 15;
    float acc[8];
#pragma unroll
    for (int j = 0; j < 8; j++) acc[j] = 0.f;
#pragma unroll
    for (int hh = 0; hh < 4; hh++) {
        int h = h2 * 4 + hh;
        float anh = __shfl_sync(0xffffffffu, an, h);
        uint4 vv = *(const uint4*)&d_vb[(size_t)src * HC + h * 128 + c8 * 8];
        float2 v0 = __bfloat1622float2(*(__nv_bfloat162*)&vv.x);
        float2 v1 = __bfloat1622float2(*(__nv_bfloat162*)&vv.y);
        float2 v2 = __bfloat1622float2(*(__nv_bfloat162*)&vv.z);
        float2 v3 = __bfloat1622float2(*(__nv_bfloat162*)&vv.w);
        acc[0] += anh * v0.x;
        acc[1] += anh * v0.y;
        acc[2] += anh * v1.x;
        acc[3] += anh * v1.y;
        acc[4] += anh * v2.x;
        acc[5] += anh * v2.y;
        acc[6] += anh * v3.x;
        acc[7] += anh * v3.y;
    }
#pragma unroll
    for (int j = 0; j < 8; j++) acc[j] += __shfl_xor_sync(0xffffffffu, acc[j], 16);
    if (h2 == 0) {
        float* outp = &d_vout[dst * 128 + c8 * 8];
        asm volatile("red.global.add.v4.f32 [%0], {%1,%2,%3,%4};\n" ::"l"(outp),
                     "f"(acc[0]), "f"(acc[1]), "f"(acc[2]), "f"(acc[3])
                     : "memory");
        asm volatile("red.global.add.v4.f32 [%0], {%1,%2,%3,%4};\n" ::"l"(outp + 4),
                     "f"(acc[4]), "f"(acc[5]), "f"(acc[6]), "f"(acc[7])
                     : "memory");
    }
    float4 ea4 = ((const float4*)&ea[e * F_EDGE])[l & 3];
    float anj = __shfl_sync(0xffffffffu, an, l >> 2);
    float* bp = &d_B[dst * 128 + l * 4];
    asm volatile("red.global.add.v4.f32 [%0], {%1,%2,%3,%4};\n" ::"l"(bp),
                 "f"(anj * ea4.x), "f"(anj * ea4.y), "f"(anj * ea4.z), "f"(anj * ea4.w)
                 : "memory");
}

// ---------------- final dot ----------------
__global__ __launch_bounds__(128) void final_dot(const float* __restrict__ Wd,
                                                 const float* __restrict__ bd,
                                                 float* __restrict__ out) {
    int t = threadIdx.x;
    float v = d_pooled[t] * Wd[t];
#pragma unroll
    for (int o = 16; o; o >>= 1) v += __shfl_xor_sync(0xffffffffu, v, o);
    __shared__ float red[4];
    if ((t & 31) == 0) red[t >> 5] = v;
    __syncthreads();
    if (t == 0) out[0] = red[0] + red[1] + red[2] + red[3] + bd[0];
}

extern "C" void kernel_launch(void* const* d_in, const int* in_sizes, int n_in,
                              void* d_out, int out_size) {
    const float* x          = (const float*)d_in[0];
    const float* edge_attr  = (const float*)d_in[1];
    const int*   edge_index = (const int*)d_in[2];
    const float* Wq = (const float*)d_in[3];
    const float* bq = (const float*)d_in[4];
    const float* Wk = (const float*)d_in[5];
    const float* bk = (const float*)d_in[6];
    const float* Wv = (const float*)d_in[7];
    const float* bv = (const float*)d_in[8];
    const float* We = (const float*)d_in[9];
    const float* Wskip = (const float*)d_in[10];
    const float* bskip = (const float*)d_in[11];
    const float* Wd = (const float*)d_in[12];
    const float* bd = (const float*)d_in[13];
    float* out = (float*)d_out;

    static void *p_vout = nullptr, *p_B = nullptr, *p_s = nullptr, *p_pooled = nullptr;
    if (!p_vout) {
        cudaFuncSetAttribute(gemm_tc, cudaFuncAttributeMaxDynamicSharedMemorySize, 60416);
        cudaGetSymbolAddress(&p_vout, d_vout);
        cudaGetSymbolAddress(&p_B, d_B);
        cudaGetSymbolAddress(&p_s, d_s);
        cudaGetSymbolAddress(&p_pooled, d_pooled);
    }

    cudaMemsetAsync(p_vout, 0, N_NODES * 128 * sizeof(float), 0);
    cudaMemsetAsync(p_B, 0, N_NODES * 128 * sizeof(float), 0);
    cudaMemsetAsync(p_s, 0, N_NODES * HEADS * sizeof(float), 0);
    cudaMemsetAsync(p_pooled, 0, 128 * sizeof(float), 0);

    prep_all<<<(PREP_TOTAL + 255) / 256, 256>>>(x, Wq, Wk, Wv, Wskip, bq, bk, bv, bskip,
                                                We);

    // fused q|k|v|skip : [10000,128] @ [128,3200]
    gemm_tc<<<dim3(50, 79), 256, 59648>>>(0, 0, 0, N_NODES, NQKVS, 128, 128);
    // g = q @ Wg (block-diag: each n-block uses its 512-wide k-slice)
    gemm_tc<<<dim3(2, 79), 256, 59648>>>(1, 1, 1, N_NODES, 128, 1024, 512);

    dim3 eblk(32, 8);
    edge_alpha<<<12500, eblk>>>(edge_attr, edge_index);
    edge_msg<<<12500, eblk>>>(edge_attr, edge_index);

    split_B<<<5000, 256>>>();
    // eterm = B @ Wer, fused relu(eterm+vout+skip) column-sum into pooled
    gemm_tc<<<dim3(2, 79), 256, 59648>>>(2, 2, 2, N_NODES, 128, 128, 128);

    final_dot<<<1, 128>>>(Wd, bd, out);
}

// round 7
// speedup vs baseline: 1.6898x; 1.6898x over previous
#include <cuda_runtime.h>
#include <cuda_bf16.h>
#include <stdint.h>
#include <math.h>

#define N_NODES 10000
#define N_EDGES 100000
#define F_NODE 128
#define F_EDGE 16
#define HEADS 8
#define OUT_CH 128
#define HC 1024
#define NQKVS 3200   // 3*1024 + 128 fused output columns

// ---------------- scratch (device globals) ----------------
__device__ __nv_bfloat16 d_xh[N_NODES * 128];
__device__ __nv_bfloat16 d_qb[N_NODES * HC];
__device__ __nv_bfloat16 d_kb[N_NODES * HC];
__device__ __nv_bfloat16 d_vb[N_NODES * HC];
__device__ __nv_bfloat16 d_Bb[N_NODES * 128];
__device__ __nv_bfloat16 d_Wqh[128 * NQKVS];
__device__ __nv_bfloat16 d_Wgh[1024 * 128];
__device__ __nv_bfloat16 d_Werh[128 * 128];
__device__ float d_biasc[NQKVS];
__device__ float d_skip[N_NODES * 128];
__device__ float d_g[N_NODES * 128];
__device__ float d_aexp[N_EDGES * HEADS];
__device__ float d_s[N_NODES * HEADS];
__device__ float d_vout[N_NODES * 128];
__device__ float d_B[N_NODES * 128];
__device__ float d_pooled[128];

// ---------------- fused prep: bf16(x) | pack_w | bias | build_wg | build_wer ----
#define SEG0 (N_NODES * 128)
#define SEG1 (128 * NQKVS)
#define SEG2 (NQKVS)
#define SEG3 (1024 * 128)
#define SEG4 (128 * 128)
#define PREP_TOTAL (SEG0 + SEG1 + SEG2 + SEG3 + SEG4)

__global__ __launch_bounds__(256) void prep_all(
    const float* __restrict__ x, const float* __restrict__ Wq,
    const float* __restrict__ Wk, const float* __restrict__ Wv,
    const float* __restrict__ Ws, const float* __restrict__ bq,
    const float* __restrict__ bk, const float* __restrict__ bv,
    const float* __restrict__ bs, const float* __restrict__ We) {
    int idx = blockIdx.x * 256 + threadIdx.x;
    if (idx < SEG0) {
        d_xh[idx] = __float2bfloat16(x[idx]);
        return;
    }
    idx -= SEG0;
    if (idx < SEG1) {
        int k = idx / NQKVS, col = idx % NQKVS;
        float v;
        if (col < 1024) v = Wq[k * HC + col];
        else if (col < 2048) v = Wk[k * HC + col - 1024];
        else if (col < 3072) v = Wv[k * HC + col - 2048];
        else v = Ws[k * 128 + col - 3072];
        d_Wqh[idx] = __float2bfloat16(v);
        return;
    }
    idx -= SEG1;
    if (idx < SEG2) {
        float b;
        if (idx < 1024) b = bq[idx];
        else if (idx < 2048) b = bk[idx - 1024];
        else if (idx < 3072) b = bv[idx - 2048];
        else b = bs[idx - 3072];
        d_biasc[idx] = b;
        return;
    }
    idx -= SEG2;
    if (idx < SEG3) {
        int k = idx >> 7, j = idx & 127;
        int h = j >> 4, f = j & 15;
        int c = k & 127, hk = k >> 7;
        float v = (hk == h) ? We[f * HC + h * 128 + c] : 0.f;
        d_Wgh[idx] = __float2bfloat16(v);
        return;
    }
    idx -= SEG3;
    if (idx < SEG4) {
        int j = idx >> 7, c = idx & 127;
        int h = j >> 4, f = j & 15;
        d_Werh[idx] = __float2bfloat16(We[f * HC + h * 128 + c]);
    }
}

__global__ void split_B() {
    int i = blockIdx.x * 256 + threadIdx.x;
    if (i < N_NODES * 128) d_Bb[i] = __float2bfloat16(d_B[i]);
}

// ---------------- MMA helpers ----------------
__device__ __forceinline__ void ldsm4(uint32_t* r, const void* p) {
    unsigned a = (unsigned)__cvta_generic_to_shared(p);
    asm volatile("ldmatrix.sync.aligned.m8n8.x4.shared.b16 {%0,%1,%2,%3}, [%4];\n"
                 : "=r"(r[0]), "=r"(r[1]), "=r"(r[2]), "=r"(r[3]) : "r"(a));
}
__device__ __forceinline__ void ldsm4t(uint32_t* r, const void* p) {
    unsigned a = (unsigned)__cvta_generic_to_shared(p);
    asm volatile("ldmatrix.sync.aligned.m8n8.x4.trans.shared.b16 {%0,%1,%2,%3}, [%4];\n"
                 : "=r"(r[0]), "=r"(r[1]), "=r"(r[2]), "=r"(r[3]) : "r"(a));
}
__device__ __forceinline__ void mma_bf16(float* c, const uint32_t* a, uint32_t b0,
                                         uint32_t b1) {
    asm volatile(
        "mma.sync.aligned.m16n8k16.row.col.f32.bf16.bf16.f32 "
        "{%0,%1,%2,%3}, {%4,%5,%6,%7}, {%8,%9}, {%0,%1,%2,%3};\n"
        : "+f"(c[0]), "+f"(c[1]), "+f"(c[2]), "+f"(c[3])
        : "r"(a[0]), "r"(a[1]), "r"(a[2]), "r"(a[3]), "r"(b0), "r"(b1));
}
__device__ __forceinline__ void cp16(void* sdst, const void* gsrc, bool pred) {
    unsigned s = (unsigned)__cvta_generic_to_shared(sdst);
    int sz = pred ? 16 : 0;
    asm volatile("cp.async.cg.shared.global [%0], [%1], 16, %2;\n" ::"r"(s), "l"(gsrc),
                 "r"(sz));
}

// ---------------- unified TC GEMM, double-buffered, single-pass bf16 ----------------
// asel: 0 = d_xh; 1 = d_qb; 2 = d_Bb.   wsel: 0 = Wqkvs; 1 = Wg; 2 = Wer.
// osel: 0 = qkv(bf16)+skip(f32); 1 = g f32; 2 = eterm fused reduce.
__global__ __launch_bounds__(256) void gemm_tc(int asel, int wsel, int osel, int M,
                                               int N, int Kstride, int kcount) {
    const __nv_bfloat16 *Ah, *Wh;
    if (asel == 0) Ah = d_xh;
    else if (asel == 1) Ah = d_qb;
    else Ah = d_Bb;
    if (wsel == 0) Wh = d_Wqh;
    else if (wsel == 1) Wh = d_Wgh;
    else Wh = d_Werh;

    extern __shared__ __align__(16) char dyn[];
    __nv_bfloat16* dynb = (__nv_bfloat16*)dyn;
    float* spool = (float*)(dyn + 29696);

    int tid = threadIdx.x, w = tid >> 5, l = tid & 31;
    int bm = blockIdx.y * 128, bn = blockIdx.x * 64;
    int wm = (w >> 1) * 32, wn = (w & 1) * 32;
    int kbeg = (wsel == 1) ? blockIdx.x * 512 : 0;
    if (osel == 2 && tid < 64) spool[tid] = 0.f;

    float acc[2][4][4];
#pragma unroll
    for (int a = 0; a < 2; a++)
#pragma unroll
        for (int b = 0; b < 4; b++)
#pragma unroll
            for (int c = 0; c < 4; c++) acc[a][b][c] = 0.f;

    int a_r = (l & 7) + ((l >> 3) & 1) * 8;
    int a_ko = ((l >> 4) & 1) * 8;

    auto pA = [&](int st) { return dynb + st * 5120; };
    auto pW = [&](int st) { return dynb + 10240 + st * 2304; };

    auto load_stage = [&](int st, int kc) {
        __nv_bfloat16* dstA = pA(st);
#pragma unroll
        for (int i = 0; i < 2; i++) {
            int idx = tid + 256 * i;
            int row = idx >> 2, ch = idx & 3;
            int gr = bm + row;
            cp16(dstA + row * 40 + ch * 8, Ah + (size_t)gr * Kstride + kc + ch * 8,
                 gr < M);
        }
        __nv_bfloat16* dstW = pW(st);
        {
            int k = tid >> 3, ch = tid & 7;
            cp16(dstW + k * 72 + ch * 8, Wh + (size_t)(kc + k) * N + bn + ch * 8, true);
        }
        asm volatile("cp.async.commit_group;\n" ::);
    };

    auto compute = [&](int st) {
#pragma unroll
        for (int k16 = 0; k16 < 2; k16++) {
            uint32_t Af[2][4], Bf[2][4];
            __nv_bfloat16* ah = pA(st);
#pragma unroll
            for (int mt = 0; mt < 2; mt++)
                ldsm4(Af[mt], ah + (wm + mt * 16 + a_r) * 40 + k16 * 16 + a_ko);
            __nv_bfloat16* wh = pW(st);
#pragma unroll
            for (int p = 0; p < 2; p++)
                ldsm4t(Bf[p], wh + (k16 * 16 + a_r) * 72 + wn + p * 16 + a_ko);
#pragma unroll
            for (int nt = 0; nt < 4; nt++) {
                uint32_t b0 = Bf[nt >> 1][(nt & 1) * 2], b1 = Bf[nt >> 1][(nt & 1) * 2 + 1];
#pragma unroll
                for (int mt = 0; mt < 2; mt++) mma_bf16(acc[mt][nt], Af[mt], b0, b1);
            }
        }
    };

    int nIter = kcount >> 5;
    load_stage(0, kbeg);
    for (int it = 0; it < nIter; it++) {
        if (it + 1 < nIter) {
            load_stage((it + 1) & 1, kbeg + (it + 1) * 32);
            asm volatile("cp.async.wait_group 1;\n" ::);
        } else {
            asm volatile("cp.async.wait_group 0;\n" ::);
        }
        __syncthreads();
        compute(it & 1);
        __syncthreads();
    }

    int r0 = l >> 2, cq = (l & 3) * 2;
    if (osel == 0) {
        __nv_bfloat16* dstb = nullptr;
        float* dstf = nullptr;
        int coff;
        if (bn < 1024) { dstb = d_qb; coff = bn; }
        else if (bn < 2048) { dstb = d_kb; coff = bn - 1024; }
        else if (bn < 3072) { dstb = d_vb; coff = bn - 2048; }
        else { dstf = d_skip; coff = bn - 3072; }
#pragma unroll
        for (int mt = 0; mt < 2; mt++)
#pragma unroll
            for (int nt = 0; nt < 4; nt++) {
                int gcol = bn + wn + nt * 8 + cq;
                int col = coff + wn + nt * 8 + cq;
                float bb0 = d_biasc[gcol], bb1 = d_biasc[gcol + 1];
#pragma unroll
                for (int rr = 0; rr < 2; rr++) {
                    int row = bm + wm + mt * 16 + r0 + rr * 8;
                    if (row < M) {
                        float v0 = acc[mt][nt][rr * 2] + bb0;
                        float v1 = acc[mt][nt][rr * 2 + 1] + bb1;
                        if (dstf) {
                            dstf[row * 128 + col] = v0;
                            dstf[row * 128 + col + 1] = v1;
                        } else {
                            *(__nv_bfloat162*)&dstb[(size_t)row * HC + col] =
                                __floats2bfloat162_rn(v0, v1);
                        }
                    }
                }
            }
    } else if (osel == 1) {
#pragma unroll
        for (int mt = 0; mt < 2; mt++)
#pragma unroll
            for (int nt = 0; nt < 4; nt++) {
                int col = bn + wn + nt * 8 + cq;
#pragma unroll
                for (int rr = 0; rr < 2; rr++) {
                    int row = bm + wm + mt * 16 + r0 + rr * 8;
                    if (row < M) {
                        d_g[row * 128 + col] = acc[mt][nt][rr * 2];
                        d_g[row * 128 + col + 1] = acc[mt][nt][rr * 2 + 1];
                    }
                }
            }
    } else {
#pragma unroll
        for (int nt = 0; nt < 4; nt++) {
            int col = bn + wn + nt * 8 + cq;
            float s0 = 0.f, s1 = 0.f;
#pragma unroll
            for (int mt = 0; mt < 2; mt++)
#pragma unroll
                for (int rr = 0; rr < 2; rr++) {
                    int row = bm + wm + mt * 16 + r0 + rr * 8;
                    if (row < M) {
                        s0 += fmaxf(acc[mt][nt][rr * 2] + d_vout[row * 128 + col] +
                                        d_skip[row * 128 + col], 0.f);
                        s1 += fmaxf(acc[mt][nt][rr * 2 + 1] + d_vout[row * 128 + col + 1] +
                                        d_skip[row * 128 + col + 1], 0.f);
                    }
                }
#pragma unroll
            for (int off = 16; off >= 4; off >>= 1) {
                s0 += __shfl_xor_sync(0xffffffffu, s0, off);
                s1 += __shfl_xor_sync(0xffffffffu, s1, off);
            }
            if (l < 4) {
                atomicAdd(&spool[wn + nt * 8 + cq], s0);
                atomicAdd(&spool[wn + nt * 8 + cq + 1], s1);
            }
        }
        __syncthreads();
        if (tid < 64) atomicAdd(&d_pooled[bn + tid], spool[tid]);
    }
}

// ---------------- edge helpers ----------------
__device__ __forceinline__ float dot8(uint4 a, uint4 b) {
    float2 a0 = __bfloat1622float2(*(__nv_bfloat162*)&a.x);
    float2 a1 = __bfloat1622float2(*(__nv_bfloat162*)&a.y);
    float2 a2 = __bfloat1622float2(*(__nv_bfloat162*)&a.z);
    float2 a3 = __bfloat1622float2(*(__nv_bfloat162*)&a.w);
    float2 b0 = __bfloat1622float2(*(__nv_bfloat162*)&b.x);
    float2 b1 = __bfloat1622float2(*(__nv_bfloat162*)&b.y);
    float2 b2 = __bfloat1622float2(*(__nv_bfloat162*)&b.z);
    float2 b3 = __bfloat1622float2(*(__nv_bfloat162*)&b.w);
    return a0.x * b0.x + a0.y * b0.y + a1.x * b1.x + a1.y * b1.y + a2.x * b2.x +
           a2.y * b2.y + a3.x * b3.x + a3.y * b3.y;
}

// ---------------- edge pass A: alpha (R4-exact quad-per-head) ----------------
__global__ __launch_bounds__(256) void edge_alpha(const float* __restrict__ ea,
                                                  const int* __restrict__ eidx) {
    int e = blockIdx.x * 8 + threadIdx.y;
    if (e >= N_EDGES) return;
    int l = threadIdx.x;
    int src = __ldg(&eidx[e]);
    int dst = __ldg(&eidx[N_EDGES + e]);
    int h = l >> 2, p = l & 3;
    const uint4* q4 = (const uint4*)&d_qb[(size_t)dst * HC + h * 128 + p * 32];
    const uint4* k4 = (const uint4*)&d_kb[(size_t)src * HC + h * 128 + p * 32];
    uint4 qa0 = q4[0], qa1 = q4[1], qa2 = q4[2], qa3 = q4[3];
    uint4 kb0 = k4[0], kb1 = k4[1], kb2 = k4[2], kb3 = k4[3];
    float4 g4 = *(const float4*)&d_g[dst * 128 + h * 16 + p * 4];
    float4 e4 = *(const float4*)&ea[e * F_EDGE + p * 4];
    float dp = dot8(qa0, kb0) + dot8(qa1, kb1) + dot8(qa2, kb2) + dot8(qa3, kb3);
    dp += g4.x * e4.x + g4.y * e4.y + g4.z * e4.z + g4.w * e4.w;
    dp += __shfl_xor_sync(0xffffffffu, dp, 1);
    dp += __shfl_xor_sync(0xffffffffu, dp, 2);
    if (p == 0) {
        float aex = __expf(dp * 0.08838834764831845f);
        d_aexp[e * 8 + h] = aex;
        atomicAdd(&d_s[dst * 8 + h], aex);
    }
}

// ---------------- edge pass B: v-term + B scatter (R4-exact) ----------------
__global__ __launch_bounds__(256) void edge_msg(const float* __restrict__ ea,
                                                const int* __restrict__ eidx) {
    int e = blockIdx.x * 8 + threadIdx.y;
    if (e >= N_EDGES) return;
    int l = threadIdx.x;
    int src = __ldg(&eidx[e]);
    int dst = __ldg(&eidx[N_EDGES + e]);
    float an = 0.f;
    if (l < 8) {
        float s = d_s[dst * 8 + l];
        an = 0.125f * d_aexp[e * 8 + l] / (s + 1e-16f);
    }
    int h2 = l >> 4, c8 = l & 15;
    float acc[8];
#pragma unroll
    for (int j = 0; j < 8; j++) acc[j] = 0.f;
#pragma unroll
    for (int hh = 0; hh < 4; hh++) {
        int h = h2 * 4 + hh;
        float anh = __shfl_sync(0xffffffffu, an, h);
        uint4 vv = *(const uint4*)&d_vb[(size_t)src * HC + h * 128 + c8 * 8];
        float2 v0 = __bfloat1622float2(*(__nv_bfloat162*)&vv.x);
        float2 v1 = __bfloat1622float2(*(__nv_bfloat162*)&vv.y);
        float2 v2 = __bfloat1622float2(*(__nv_bfloat162*)&vv.z);
        float2 v3 = __bfloat1622float2(*(__nv_bfloat162*)&vv.w);
        acc[0] += anh * v0.x;
        acc[1] += anh * v0.y;
        acc[2] += anh * v1.x;
        acc[3] += anh * v1.y;
        acc[4] += anh * v2.x;
        acc[5] += anh * v2.y;
        acc[6] += anh * v3.x;
        acc[7] += anh * v3.y;
    }
#pragma unroll
    for (int j = 0; j < 8; j++) acc[j] += __shfl_xor_sync(0xffffffffu, acc[j], 16);
    if (h2 == 0) {
        float* outp = &d_vout[dst * 128 + c8 * 8];
        asm volatile("red.global.add.v4.f32 [%0], {%1,%2,%3,%4};\n" ::"l"(outp),
                     "f"(acc[0]), "f"(acc[1]), "f"(acc[2]), "f"(acc[3])
                     : "memory");
        asm volatile("red.global.add.v4.f32 [%0], {%1,%2,%3,%4};\n" ::"l"(outp + 4),
                     "f"(acc[4]), "f"(acc[5]), "f"(acc[6]), "f"(acc[7])
                     : "memory");
    }
    float4 ea4 = ((const float4*)&ea[e * F_EDGE])[l & 3];
    float anj = __shfl_sync(0xffffffffu, an, l >> 2);
    float* bp = &d_B[dst * 128 + l * 4];
    asm volatile("red.global.add.v4.f32 [%0], {%1,%2,%3,%4};\n" ::"l"(bp),
                 "f"(anj * ea4.x), "f"(anj * ea4.y), "f"(anj * ea4.z), "f"(anj * ea4.w)
                 : "memory");
}

// ---------------- final dot ----------------
__global__ __launch_bounds__(128) void final_dot(const float* __restrict__ Wd,
                                                 const float* __restrict__ bd,
                                                 float* __restrict__ out) {
    int t = threadIdx.x;
    float v = d_pooled[t] * Wd[t];
#pragma unroll
    for (int o = 16; o; o >>= 1) v += __shfl_xor_sync(0xffffffffu, v, o);
    __shared__ float red[4];
    if ((t & 31) == 0) red[t >> 5] = v;
    __syncthreads();
    if (t == 0) out[0] = red[0] + red[1] + red[2] + red[3] + bd[0];
}

extern "C" void kernel_launch(void* const* d_in, const int* in_sizes, int n_in,
                              void* d_out, int out_size) {
    const float* x          = (const float*)d_in[0];
    const float* edge_attr  = (const float*)d_in[1];
    const int*   edge_index = (const int*)d_in[2];
    const float* Wq = (const float*)d_in[3];
    const float* bq = (const float*)d_in[4];
    const float* Wk = (const float*)d_in[5];
    const float* bk = (const float*)d_in[6];
    const float* Wv = (const float*)d_in[7];
    const float* bv = (const float*)d_in[8];
    const float* We = (const float*)d_in[9];
    const float* Wskip = (const float*)d_in[10];
    const float* bskip = (const float*)d_in[11];
    const float* Wd = (const float*)d_in[12];
    const float* bd = (const float*)d_in[13];
    float* out = (float*)d_out;

    static void *p_vout = nullptr, *p_B = nullptr, *p_s = nullptr, *p_pooled = nullptr;
    if (!p_vout) {
        cudaFuncSetAttribute(gemm_tc, cudaFuncAttributeMaxDynamicSharedMemorySize, 30720);
        cudaGetSymbolAddress(&p_vout, d_vout);
        cudaGetSymbolAddress(&p_B, d_B);
        cudaGetSymbolAddress(&p_s, d_s);
        cudaGetSymbolAddress(&p_pooled, d_pooled);
    }

    cudaMemsetAsync(p_vout, 0, N_NODES * 128 * sizeof(float), 0);
    cudaMemsetAsync(p_B, 0, N_NODES * 128 * sizeof(float), 0);
    cudaMemsetAsync(p_s, 0, N_NODES * HEADS * sizeof(float), 0);
    cudaMemsetAsync(p_pooled, 0, 128 * sizeof(float), 0);

    prep_all<<<(PREP_TOTAL + 255) / 256, 256>>>(x, Wq, Wk, Wv, Wskip, bq, bk, bv, bskip,
                                                We);

    // fused q|k|v|skip : [10000,128] @ [128,3200], single-pass bf16
    gemm_tc<<<dim3(50, 79), 256, 29952>>>(0, 0, 0, N_NODES, NQKVS, 128, 128);
    // g = q @ Wg (block-diag: each n-block uses its 512-wide k-slice)
    gemm_tc<<<dim3(2, 79), 256, 29952>>>(1, 1, 1, N_NODES, 128, 1024, 512);

    dim3 eblk(32, 8);
    edge_alpha<<<12500, eblk>>>(edge_attr, edge_index);
    edge_msg<<<12500, eblk>>>(edge_attr, edge_index);

    split_B<<<5000, 256>>>();
    // eterm = B @ Wer, fused relu(eterm+vout+skip) column-sum into pooled
    gemm_tc<<<dim3(2, 79), 256, 29952>>>(2, 2, 2, N_NODES, 128, 128, 128);

    final_dot<<<1, 128>>>(Wd, bd, out);
}